// round 2
// baseline (speedup 1.0000x reference)
#include <cuda_runtime.h>
#include <cuda_bf16.h>

#define B_  16
#define S_  80
#define D_  512
#define H_  64
#define G4_ 256    /* 4*H */
#define DI_ 2048
#define L_  6
#define M_  (B_*S_)   /* 1280 rows */
#define NS  4         /* samples per LSTM block */

typedef unsigned long long ull;

// ---------------- scratch (static device globals; no allocation) ----------------
__device__ float g_x [M_*D_];   // current activations (residual stream)
__device__ float g_xn[M_*D_];   // layernorm output
__device__ float g_xg[M_*G4_];  // input-gate projections, layout [(s*16+b)*256+g]
__device__ float g_h [M_*H_];   // LSTM final hidden, layout [(i*16+b)*64+k]
__device__ float g_y [M_*DI_];  // FFN hidden

// ---------------- helpers ----------------
__device__ __forceinline__ ull fma2(ull a, ull b, ull c) {
    ull d; asm("fma.rn.f32x2 %0, %1, %2, %3;" : "=l"(d) : "l"(a), "l"(b), "l"(c)); return d;
}
__device__ __forceinline__ ull f2u(float a, float b) {
    ull u; asm("mov.b64 %0, {%1, %2};" : "=l"(u) : "f"(a), "f"(b)); return u;
}
__device__ __forceinline__ float2 u2f(ull u) {
    float2 f; asm("mov.b64 {%0, %1}, %2;" : "=f"(f.x), "=f"(f.y) : "l"(u)); return f;
}
__device__ __forceinline__ float fast_ex2(float x) {
    float r; asm("ex2.approx.f32 %0, %1;" : "=f"(r) : "f"(x)); return r;
}
__device__ __forceinline__ float fast_rcp(float x) {
    float r; asm("rcp.approx.f32 %0, %1;" : "=f"(r) : "f"(x)); return r;
}
__device__ __forceinline__ float sigf(float x) {
    return fast_rcp(1.0f + fast_ex2(-1.4426950408889634f * x));
}
__device__ __forceinline__ float tanhf_(float x) {
    return fmaf(2.0f, sigf(2.0f * x), -1.0f);
}

// ---------------- layernorm: one block per row of 512 ----------------
__global__ void __launch_bounds__(128) ln_kernel(
    const float* __restrict__ x, float* __restrict__ y,
    const float* __restrict__ gw, const float* __restrict__ bw)
{
    const int row = blockIdx.x, t = threadIdx.x;
    const float4 v = *(const float4*)(x + (size_t)row * D_ + t * 4);
    float s  = v.x + v.y + v.z + v.w;
    float ss = v.x*v.x + v.y*v.y + v.z*v.z + v.w*v.w;
#pragma unroll
    for (int o = 16; o > 0; o >>= 1) {
        s  += __shfl_xor_sync(0xffffffffu, s,  o);
        ss += __shfl_xor_sync(0xffffffffu, ss, o);
    }
    __shared__ float rs[4], rss[4];
    const int w = t >> 5, lane = t & 31;
    if (lane == 0) { rs[w] = s; rss[w] = ss; }
    __syncthreads();
    s  = rs[0] + rs[1] + rs[2] + rs[3];
    ss = rss[0] + rss[1] + rss[2] + rss[3];
    const float mean = s * (1.0f / D_);
    const float var  = ss * (1.0f / D_) - mean * mean;
    const float rstd = rsqrtf(var + 1e-6f);
    const float4 g4 = *(const float4*)(gw + t * 4);
    const float4 b4 = *(const float4*)(bw + t * 4);
    float4 o4;
    o4.x = (v.x - mean) * rstd * g4.x + b4.x;
    o4.y = (v.y - mean) * rstd * g4.y + b4.y;
    o4.z = (v.z - mean) * rstd * g4.z + b4.z;
    o4.w = (v.w - mean) * rstd * g4.w + b4.w;
    *(float4*)(y + (size_t)row * D_ + t * 4) = o4;
}

// ---------------- final layernorm + projection to 1 ----------------
__global__ void __launch_bounds__(128) final_kernel(
    const float* __restrict__ x, const float* __restrict__ gw,
    const float* __restrict__ bw, const float* __restrict__ wp,
    float* __restrict__ out)
{
    const int row = blockIdx.x, t = threadIdx.x;
    const float4 v = *(const float4*)(x + (size_t)row * D_ + t * 4);
    float s  = v.x + v.y + v.z + v.w;
    float ss = v.x*v.x + v.y*v.y + v.z*v.z + v.w*v.w;
#pragma unroll
    for (int o = 16; o > 0; o >>= 1) {
        s  += __shfl_xor_sync(0xffffffffu, s,  o);
        ss += __shfl_xor_sync(0xffffffffu, ss, o);
    }
    __shared__ float rs[4], rss[4], rd[4];
    const int w = t >> 5, lane = t & 31;
    if (lane == 0) { rs[w] = s; rss[w] = ss; }
    __syncthreads();
    s  = rs[0] + rs[1] + rs[2] + rs[3];
    ss = rss[0] + rss[1] + rss[2] + rss[3];
    const float mean = s * (1.0f / D_);
    const float var  = ss * (1.0f / D_) - mean * mean;
    const float rstd = rsqrtf(var + 1e-6f);
    const float4 g4 = *(const float4*)(gw + t * 4);
    const float4 b4 = *(const float4*)(bw + t * 4);
    const float4 w4 = *(const float4*)(wp + t * 4);
    float d = ((v.x - mean) * rstd * g4.x + b4.x) * w4.x
            + ((v.y - mean) * rstd * g4.y + b4.y) * w4.y
            + ((v.z - mean) * rstd * g4.z + b4.z) * w4.z
            + ((v.w - mean) * rstd * g4.w + b4.w) * w4.w;
#pragma unroll
    for (int o = 16; o > 0; o >>= 1) d += __shfl_xor_sync(0xffffffffu, d, o);
    if (lane == 0) rd[w] = d;
    __syncthreads();
    if (t == 0) out[row] = rd[0] + rd[1] + rd[2] + rd[3];
}

// ---------------- generic GEMM: C = A(MxK) * B(NxK)^T (+bias)(relu)(+resid) ----
// APERM: A row m is read from row (m%80)*16 + m/80  (LSTM hidden -> [b,s] order)
// CPERM: C row m is written to row (m%80)*16 + m/80 ([b,s] -> [s,b] for xg)
template<bool RELU, bool BIAS, bool RESID, bool APERM, bool CPERM>
__global__ void __launch_bounds__(256) gemm_kernel(
    const float* __restrict__ A, const float* __restrict__ Bm,
    const float* __restrict__ bias, const float* __restrict__ resid,
    float* __restrict__ C, int K, int N)
{
    __shared__ float As[16][130];   // A duplicated: As[k][2m]=As[k][2m+1]=A[m][k]
    __shared__ float Bs[16][68];
    const int tid = threadIdx.x;
    const int tx = tid & 15, ty = tid >> 4;
    const int m0 = blockIdx.y * 64, n0 = blockIdx.x * 64;

    const int lr = tid >> 2;           // 0..63: tile row
    const int lk = (tid & 3) << 2;     // 0,4,8,12: k offset of float4

    int am = m0 + lr;
    if (APERM) am = (am % S_) * B_ + am / S_;
    const float* Ap = A  + (size_t)am * K + lk;
    const float* Bp = Bm + (size_t)(n0 + lr) * K + lk;

    ull acc[4][2] = {};

    for (int k0 = 0; k0 < K; k0 += 16) {
        const float4 av = *(const float4*)(Ap + k0);
        const float4 bv = *(const float4*)(Bp + k0);
        __syncthreads();
        *(ull*)&As[lk + 0][2 * lr] = f2u(av.x, av.x);
        *(ull*)&As[lk + 1][2 * lr] = f2u(av.y, av.y);
        *(ull*)&As[lk + 2][2 * lr] = f2u(av.z, av.z);
        *(ull*)&As[lk + 3][2 * lr] = f2u(av.w, av.w);
        Bs[lk + 0][lr] = bv.x;
        Bs[lk + 1][lr] = bv.y;
        Bs[lk + 2][lr] = bv.z;
        Bs[lk + 3][lr] = bv.w;
        __syncthreads();
#pragma unroll
        for (int k = 0; k < 16; k++) {
            const ull a0 = *(const ull*)&As[k][(ty * 4 + 0) * 2];
            const ull a1 = *(const ull*)&As[k][(ty * 4 + 1) * 2];
            const ull a2 = *(const ull*)&As[k][(ty * 4 + 2) * 2];
            const ull a3 = *(const ull*)&As[k][(ty * 4 + 3) * 2];
            const ulonglong2 bb = *(const ulonglong2*)&Bs[k][tx * 4];
            acc[0][0] = fma2(a0, bb.x, acc[0][0]); acc[0][1] = fma2(a0, bb.y, acc[0][1]);
            acc[1][0] = fma2(a1, bb.x, acc[1][0]); acc[1][1] = fma2(a1, bb.y, acc[1][1]);
            acc[2][0] = fma2(a2, bb.x, acc[2][0]); acc[2][1] = fma2(a2, bb.y, acc[2][1]);
            acc[3][0] = fma2(a3, bb.x, acc[3][0]); acc[3][1] = fma2(a3, bb.y, acc[3][1]);
        }
    }

#pragma unroll
    for (int i = 0; i < 4; i++) {
        const int m = m0 + ty * 4 + i;
        const float2 v0 = u2f(acc[i][0]), v1 = u2f(acc[i][1]);
        float vals[4] = { v0.x, v0.y, v1.x, v1.y };
        const int cm = CPERM ? ((m % S_) * B_ + m / S_) : m;
#pragma unroll
        for (int j = 0; j < 4; j++) {
            const int n = n0 + tx * 4 + j;
            float v = vals[j];
            if (BIAS)  v += bias[n];
            if (RELU)  v  = fmaxf(v, 0.0f);
            if (RESID) v += resid[(size_t)m * N + n];
            C[(size_t)cm * N + n] = v;
        }
    }
}

// ---------------- LSTM: whh in registers, 4 samples/block, 80 steps ------------
// gx layout: [(src*16 + b)*256 + g].  Permutation P[i]: identity with i<->79 swap.
__global__ void __launch_bounds__(256) lstm_kernel(
    const float* __restrict__ gx, const float* __restrict__ whh,
    float* __restrict__ hout)
{
    const int tid = threadIdx.x;             // gate row g = tid (0..255)
    const int n0  = blockIdx.x * NS;

    // whh row tid -> 32 packed f32x2 registers
    ull w[32];
    {
        const ulonglong2* wp = (const ulonglong2*)(whh + (size_t)tid * H_);
#pragma unroll
        for (int j = 0; j < 16; j++) {
            const ulonglong2 q = wp[j];
            w[2 * j] = q.x; w[2 * j + 1] = q.y;
        }
    }

    __shared__ __align__(16) float sh[NS][H_];
    __shared__ float sgate[NS][G4_];

    const int my_s = tid >> 6, my_k = tid & 63;   // elementwise assignment
    float c = 0.0f, hval = 0.0f;
    sh[my_s][my_k] = 0.0f;                        // 256 threads == NS*64

    int ii[NS], bb[NS];
#pragma unroll
    for (int s = 0; s < NS; s++) { const int n = n0 + s; ii[s] = n >> 4; bb[s] = n & 15; }
    __syncthreads();

    for (int t = 0; t < S_; t++) {
        float gxv[NS];
#pragma unroll
        for (int s = 0; s < NS; s++) {
            const int src = (t == ii[s]) ? (S_ - 1) : ((t == S_ - 1) ? ii[s] : t);
            gxv[s] = __ldg(gx + (size_t)(src * B_ + bb[s]) * G4_ + tid);
        }
#pragma unroll
        for (int s = 0; s < NS; s++) {
            const ull* hp = (const ull*)sh[s];
            ull acc = 0ull;
#pragma unroll
            for (int j = 0; j < 32; j++) acc = fma2(w[j], hp[j], acc);
            const float2 p = u2f(acc);
            sgate[s][tid] = gxv[s] + p.x + p.y;
        }
        __syncthreads();   // gates written & all reads of sh done
        const float iv = sgate[my_s][my_k];
        const float fv = sgate[my_s][64 + my_k];
        const float gv = sgate[my_s][128 + my_k];
        const float ov = sgate[my_s][192 + my_k];
        c    = sigf(fv) * c + sigf(iv) * tanhf_(gv);
        hval = sigf(ov) * tanhf_(c);
        sh[my_s][my_k] = hval;
        __syncthreads();   // h visible for next step, sgate reads done
    }
    hout[(size_t)(n0 + my_s) * H_ + my_k] = hval;
}

// ---------------- launch ----------------
extern "C" void kernel_launch(void* const* d_in, const int* in_sizes, int n_in,
                              void* d_out, int out_size)
{
    const float* src  = (const float*)d_in[0];
    const float* ln1g = (const float*)d_in[2];
    const float* ln1b = (const float*)d_in[3];
    const float* wih  = (const float*)d_in[4];
    const float* whh  = (const float*)d_in[5];
    const float* wfc  = (const float*)d_in[6];
    const float* ln2g = (const float*)d_in[7];
    const float* ln2b = (const float*)d_in[8];
    const float* w1   = (const float*)d_in[9];
    const float* b1   = (const float*)d_in[10];
    const float* w2   = (const float*)d_in[11];
    const float* b2   = (const float*)d_in[12];
    const float* lnfg = (const float*)d_in[13];
    const float* lnfb = (const float*)d_in[14];
    const float* wprj = (const float*)d_in[15];
    float* out = (float*)d_out;

    float *px, *pxn, *pxg, *ph, *py;
    cudaGetSymbolAddress((void**)&px,  g_x);
    cudaGetSymbolAddress((void**)&pxn, g_xn);
    cudaGetSymbolAddress((void**)&pxg, g_xg);
    cudaGetSymbolAddress((void**)&ph,  g_h);
    cudaGetSymbolAddress((void**)&py,  g_y);

    cudaMemcpyAsync(px, src, (size_t)M_ * D_ * sizeof(float),
                    cudaMemcpyDeviceToDevice, 0);

    for (int l = 0; l < L_; l++) {
        // x -> LN1 -> xn
        ln_kernel<<<M_, 128>>>(px, pxn, ln1g + l * D_, ln1b + l * D_);
        // xg[s,b,g] = xn @ wih^T   (C rows permuted to [s,b] order)
        gemm_kernel<false, false, false, false, true>
            <<<dim3(G4_ / 64, M_ / 64), 256>>>(
                pxn, wih + (size_t)l * G4_ * D_, nullptr, nullptr, pxg, D_, G4_);
        // Janossy LSTM over 80 steps
        lstm_kernel<<<M_ / NS, 256>>>(pxg, whh + (size_t)l * G4_ * H_, ph);
        // x = h @ wfc^T + x   (A rows permuted from [i*16+b] to [b*80+i] order)
        gemm_kernel<false, false, true, true, false>
            <<<dim3(D_ / 64, M_ / 64), 256>>>(
                ph, wfc + (size_t)l * D_ * H_, nullptr, px, px, H_, D_);
        // x -> LN2 -> xn
        ln_kernel<<<M_, 128>>>(px, pxn, ln2g + l * D_, ln2b + l * D_);
        // y = relu(xn @ w1^T + b1)
        gemm_kernel<true, true, false, false, false>
            <<<dim3(DI_ / 64, M_ / 64), 256>>>(
                pxn, w1 + (size_t)l * DI_ * D_, b1 + l * DI_, nullptr, py, D_, DI_);
        // x = y @ w2^T + b2 + x
        gemm_kernel<false, true, true, false, false>
            <<<dim3(D_ / 64, M_ / 64), 256>>>(
                py, w2 + (size_t)l * D_ * DI_, b2 + l * D_, px, px, DI_, D_);
    }
    final_kernel<<<M_, 128>>>(px, lnfg, lnfb, wprj, out);
}